// round 5
// baseline (speedup 1.0000x reference)
#include <cuda_runtime.h>
#include <math_constants.h>

#define NROI   1500
#define NCLS   80          // foreground classes 1..80
#define NTOT   (NROI*NCLS) // 120000
#define SCORE_THRESH 0.05f
#define NMS_THRESH   0.5f
#define MAX_DET 100
#define CAP    1504        // max valid per class (<= NROI), padded
#define MASK_CAP 512       // bitmask NMS path supported up to this nv
#define RANK_CAP 512       // rank-sort path supported up to this nv

// Output float4 quads split across the NCLS blocks
#define QTOT   ((NTOT*8)/4)        // 240000
#define QPB    (QTOT/NCLS)         // 3000 per block

// ---------------- scratch (device globals; no allocation) ----------------
// g_kcount / g_done are zero-initialized at load and restored to 0 at the end
// of every run -> every invocation (correctness, capture, replays) sees 0.
__device__ float g_ksc[NTOT];      // compacted kept scores
__device__ float g_list[NTOT*8];   // kept entries: {s, c, j, x1, y1, x2, y2, 0}
__device__ int   g_kcount;
__device__ int   g_done;

__device__ __forceinline__ unsigned int mono_key(float s) {
    unsigned int b = __float_as_uint(s);
    return (b & 0x80000000u) ? ~b : (b | 0x80000000u);
}
__device__ __forceinline__ float inv_mono(unsigned int u) {
    unsigned int b = (u & 0x80000000u) ? (u & 0x7FFFFFFFu) : ~u;
    return __uint_as_float(b);
}

struct SMem {
    unsigned long long skey[2048];
    float sx1[CAP], sy1[CAP], sx2[CAP], sy2[CAP], sar[CAP], ssc[CAP];
    unsigned long long smask[MASK_CAP*8];  // reused as sup[] bytes in fallback
    unsigned long long skeep[24];
    int   cnt;
};

__device__ __forceinline__ void decode_one(const float* __restrict__ rois,
                                           const float* __restrict__ delta,
                                           int idx, int cls, float s,
                                           float lx, float ly,
                                           SMem& sm, int r) {
    float x1 = rois[idx*5+1], y1 = rois[idx*5+2];
    float x2 = rois[idx*5+3], y2 = rois[idx*5+4];
    float w  = x2 - x1 + 1.0f;
    float h  = y2 - y1 + 1.0f;
    float cx = x1 + 0.5f*w;
    float cy = y1 + 0.5f*h;

    const float4 d4 = *reinterpret_cast<const float4*>(delta + (size_t)idx*(4*81) + 4*cls);
    float dx = d4.x / 10.0f, dy = d4.y / 10.0f;
    float dw = d4.z / 5.0f,  dh = d4.w / 5.0f;

    float pcx = cx + w*dx;
    float pcy = cy + h*dy;
    float pw  = w * expf(dw);
    float ph  = h * expf(dh);

    float bx1 = fminf(fmaxf(pcx - 0.5f*pw,        0.0f), lx);
    float by1 = fminf(fmaxf(pcy - 0.5f*ph,        0.0f), ly);
    float bx2 = fminf(fmaxf(pcx + 0.5f*pw - 1.0f, 0.0f), lx);
    float by2 = fminf(fmaxf(pcy + 0.5f*ph - 1.0f, 0.0f), ly);

    sm.sx1[r] = bx1; sm.sy1[r] = by1; sm.sx2[r] = bx2; sm.sy2[r] = by2;
    sm.sar[r] = (bx2 - bx1 + 1.0f) * (by2 - by1 + 1.0f);
    sm.ssc[r] = s;
}

__global__ __launch_bounds__(256) void k_all(const float* __restrict__ rois,
                                             const float* __restrict__ delta,
                                             const float* __restrict__ prob,
                                             const float* __restrict__ iminfo,
                                             float* __restrict__ out) {
    extern __shared__ char smem_raw[];
    SMem& sm = *reinterpret_cast<SMem*>(smem_raw);
    const int c   = blockIdx.x;
    const int cls = c + 1;
    const int tid = threadIdx.x;

    if (tid == 0) sm.cnt = 0;
    __syncthreads();

    // ---- fill this block's 1/NCLS slice of the output ----
    // layout (float32): dets[NTOT*6]=0 | cls_idx[NTOT]=class | keep[NTOT]=0
    {
        float4* o4 = reinterpret_cast<float4*>(out);
        const int q0 = c*QPB, q1 = q0 + QPB;
        for (int q = q0 + tid; q < q1; q += 256) {
            float4 v = make_float4(0.f,0.f,0.f,0.f);
            if (q >= (NTOT*6)/4 && q < (NTOT*7)/4) {
                int r0 = q*4 - NTOT*6;
                v.x = (float)((r0+0)/NROI + 1);
                v.y = (float)((r0+1)/NROI + 1);
                v.z = (float)((r0+2)/NROI + 1);
                v.w = (float)((r0+3)/NROI + 1);
            }
            o4[q] = v;
        }
    }

    // ---- compact valid entries as (score,idx) keys ----
    for (int j = tid; j < NROI; j += 256) {
        float s = prob[(size_t)j*81 + cls];
        if (s > SCORE_THRESH) {
            int p = atomicAdd(&sm.cnt, 1);
            sm.skey[p] = ((unsigned long long)mono_key(s) << 32)
                       | (unsigned long long)(0xFFFFFFFFu - (unsigned)j);
        }
    }
    __syncthreads();
    const int nv = sm.cnt;

    if (nv > 0) {
        const float H = iminfo[0], W = iminfo[1];
        const float lx = W - 1.0f, ly = H - 1.0f;

        if (nv <= RANK_CAP) {
            // ---- rank sort: descending rank = #{keys > mine}; keys unique ----
            for (int j = tid; j < nv; j += 256) {
                unsigned long long k = sm.skey[j];
                int r = 0;
                for (int i = 0; i < nv; i++) r += (sm.skey[i] > k);
                int idx = (int)(0xFFFFFFFFu - (unsigned int)(k & 0xFFFFFFFFull));
                float s = inv_mono((unsigned int)(k >> 32));
                decode_one(rois, delta, idx, cls, s, lx, ly, sm, r);
            }
            __syncthreads();
        } else {
            // ---- fallback: bitonic sort over m = next pow2 >= nv ----
            int m = 1; while (m < nv) m <<= 1;
            for (int j = nv + tid; j < m; j += 256) sm.skey[j] = 0ull; // pads last
            __syncthreads();
            for (int size = 2; size <= m; size <<= 1) {
                for (int stride = size >> 1; stride > 0; stride >>= 1) {
                    for (int t = tid; t < (m >> 1); t += 256) {
                        int pos = 2*t - (t & (stride - 1));
                        bool desc = (pos & size) == 0;
                        unsigned long long a = sm.skey[pos], b = sm.skey[pos + stride];
                        if ((a < b) == desc) { sm.skey[pos] = b; sm.skey[pos + stride] = a; }
                    }
                    __syncthreads();
                }
            }
            for (int j = tid; j < nv; j += 256) {
                unsigned long long k = sm.skey[j];
                int idx = (int)(0xFFFFFFFFu - (unsigned int)(k & 0xFFFFFFFFull));
                float s = inv_mono((unsigned int)(k >> 32));
                decode_one(rois, delta, idx, cls, s, lx, ly, sm, j);
            }
            __syncthreads();
        }

        // ---- NMS ----
        if (nv <= MASK_CAP) {
            const int MW = (nv + 63) >> 6;
            for (int i = tid; i < nv; i += 256) {
                float x1 = sm.sx1[i], y1 = sm.sy1[i], x2 = sm.sx2[i], y2 = sm.sy2[i];
                float ai = sm.sar[i];
                unsigned long long row[8];
                #pragma unroll
                for (int w = 0; w < 8; w++) row[w] = 0ull;
                for (int j = i + 1; j < nv; j++) {
                    float iw = fminf(x2, sm.sx2[j]) - fmaxf(x1, sm.sx1[j]) + 1.0f;
                    float ih = fminf(y2, sm.sy2[j]) - fmaxf(y1, sm.sy1[j]) + 1.0f;
                    iw = fmaxf(iw, 0.0f);
                    ih = fmaxf(ih, 0.0f);
                    float inter = iw * ih;
                    float iou = inter / (ai + sm.sar[j] - inter);
                    if (iou > NMS_THRESH) row[j >> 6] |= (1ull << (j & 63));
                }
                #pragma unroll
                for (int w = 0; w < 8; w++) sm.smask[i*8 + w] = row[w];
            }
            __syncthreads();
            if (tid == 0) {
                unsigned long long keepw[8], supw[8];
                #pragma unroll
                for (int w = 0; w < 8; w++) { keepw[w] = 0ull; supw[w] = 0ull; }
                for (int i = 0; i < nv; i++) {
                    if (!((supw[i >> 6] >> (i & 63)) & 1ull)) {
                        keepw[i >> 6] |= (1ull << (i & 63));
                        for (int w = (i >> 6); w < MW; w++) supw[w] |= sm.smask[i*8 + w];
                    }
                }
                for (int w = 0; w < MW; w++) sm.skeep[w] = keepw[w];
            }
            __syncthreads();
        } else {
            unsigned char* sup = reinterpret_cast<unsigned char*>(sm.smask);
            for (int j = tid; j < nv; j += 256) sup[j] = 0;
            if (tid < 24) sm.skeep[tid] = 0ull;
            __syncthreads();
            int i = 0;
            while (i < nv) {
                if (tid == 0) sm.skeep[i >> 6] |= (1ull << (i & 63));
                float x1 = sm.sx1[i], y1 = sm.sy1[i], x2 = sm.sx2[i], y2 = sm.sy2[i];
                float ai = sm.sar[i];
                for (int j = i + 1 + tid; j < nv; j += 256) {
                    if (sup[j]) continue;
                    float iw = fminf(x2, sm.sx2[j]) - fmaxf(x1, sm.sx1[j]) + 1.0f;
                    float ih = fminf(y2, sm.sy2[j]) - fmaxf(y1, sm.sy1[j]) + 1.0f;
                    iw = fmaxf(iw, 0.0f);
                    ih = fmaxf(ih, 0.0f);
                    float inter = iw * ih;
                    float iou = inter / (ai + sm.sar[j] - inter);
                    if (iou > NMS_THRESH) sup[j] = 1;
                }
                __syncthreads();
                ++i;
                while (i < nv && sup[i]) ++i;
            }
        }

        // ---- append kept entries to global list ----
        for (int j = tid; j < nv; j += 256) {
            if ((sm.skeep[j >> 6] >> (j & 63)) & 1ull) {
                int p = atomicAdd(&g_kcount, 1);
                g_ksc[p] = sm.ssc[j];
                float4* L = reinterpret_cast<float4*>(g_list + (size_t)p*8);
                L[0] = make_float4(sm.ssc[j], (float)c, (float)j, sm.sx1[j]);
                L[1] = make_float4(sm.sy1[j], sm.sx2[j], sm.sy2[j], 0.f);
            }
        }
    }

    // ================= last-block final phase =================
    __syncthreads();
    __threadfence();
    __shared__ int s_last;
    if (tid == 0) s_last = (atomicAdd(&g_done, 1) == NCLS - 1);
    __syncthreads();
    if (!s_last) return;
    __threadfence();

    const int count = atomicAdd(&g_kcount, 0);

    int   filt = 0;
    float kth  = -CUDART_INF_F;

    if (count > MAX_DET) {
        // radix select over the monotone key: 4 levels of 8-bit digits
        __shared__ int hist[256];
        __shared__ int wtot[8];
        __shared__ unsigned int s_prefix;
        __shared__ int s_need;
        if (tid == 0) { s_prefix = 0u; s_need = MAX_DET; }
        __syncthreads();

        const int lane = tid & 31, w = tid >> 5;
        #pragma unroll
        for (int level = 0; level < 4; ++level) {
            const int shift = 24 - 8*level;
            const unsigned int dmask = (level == 0) ? 0u : (0xFFFFFFFFu << (shift + 8));
            hist[tid] = 0;
            __syncthreads();
            const unsigned int pfx = s_prefix;
            const int need = s_need;
            for (int j = tid; j < count; j += 256) {
                unsigned int u = mono_key(g_ksc[j]);   // L2-hot (just written)
                if ((u & dmask) == pfx)
                    atomicAdd(&hist[(u >> shift) & 0xFFu], 1);
            }
            __syncthreads();
            int h = hist[tid];
            // warp suffix scan (8 warps x 32 bins)
            int v = h;
            #pragma unroll
            for (int off = 1; off < 32; off <<= 1) {
                int u = __shfl_down_sync(0xFFFFFFFFu, v, off);
                if (lane + off < 32) v += u;
            }
            if (lane == 0) wtot[w] = v;
            __syncthreads();
            int add = 0;
            #pragma unroll
            for (int k = 0; k < 8; k++) if (k > w) add += wtot[k];
            int sfx = v + add;            // sum of hist[tid..255]
            int hi  = sfx - h;            // sum of hist[tid+1..255]
            if (sfx >= need && hi < need) {   // unique chosen bin
                s_prefix = pfx | ((unsigned int)tid << shift);
                s_need   = need - hi;
            }
            __syncthreads();
        }
        filt = 1;
        kth  = inv_mono(s_prefix);        // exact value of the MAX_DET-th largest
    }

    // ---- scatter kept rows into the output ----
    for (int e = tid; e < count; e += 256) {
        const float4 L0 = reinterpret_cast<const float4*>(g_list + (size_t)e*8)[0];
        const float4 L1 = reinterpret_cast<const float4*>(g_list + (size_t)e*8)[1];
        float s = L0.x;
        if (filt && !(s >= kth)) continue;
        int cc = (int)L0.y;
        int jj = (int)L0.z;
        int r = cc*NROI + jj;
        float* d = out + (size_t)r*6;
        d[0] = 0.0f;
        d[1] = L0.w;  // x1
        d[2] = L1.x;  // y1
        d[3] = L1.y;  // x2
        d[4] = L1.z;  // y2
        d[5] = s;
        out[NTOT*7 + r] = 1.0f;   // keep flag
    }

    // ---- restore invariants for the next invocation ----
    __syncthreads();
    if (tid == 0) { g_kcount = 0; g_done = 0; }
}

extern "C" void kernel_launch(void* const* d_in, const int* in_sizes, int n_in,
                              void* d_out, int out_size) {
    const float* rois   = (const float*)d_in[0];
    const float* delta  = (const float*)d_in[1];
    const float* prob   = (const float*)d_in[2];
    const float* iminfo = (const float*)d_in[3];
    float* out = (float*)d_out;

    static_assert(sizeof(SMem) < 100*1024, "smem budget");
    cudaFuncSetAttribute(k_all, cudaFuncAttributeMaxDynamicSharedMemorySize,
                         (int)sizeof(SMem));

    k_all<<<NCLS, 256, sizeof(SMem)>>>(rois, delta, prob, iminfo, out);
}

// round 6
// speedup vs baseline: 1.0325x; 1.0325x over previous
#include <cuda_runtime.h>
#include <math_constants.h>

#define NROI   1500
#define NCLS   80          // foreground classes 1..80
#define NTOT   (NROI*NCLS) // 120000
#define SCORE_THRESH 0.05f
#define NMS_THRESH   0.5f
#define MAX_DET 100
#define CAP    1504        // max valid per class (<= NROI), padded
#define MASK_CAP 512       // bitmask NMS path supported up to this nv
#define RANK_CAP 512       // rank-sort path supported up to this nv
#define SEGCAP 1504        // per-class kept-entry capacity
#define THREADS 512

// Output float4 quads split across the NCLS blocks
#define QTOT   ((NTOT*8)/4)        // 240000
#define QPB    (QTOT/NCLS)         // 3000 per block

// ---------------- scratch (device globals; no allocation) ----------------
// g_done is zero-initialized at load and restored to 0 at the end of every
// run. g_segcnt[] is (re)written unconditionally by every run.
__device__ float g_segsc[NCLS*SEGCAP];    // kept scores, per-class segments
__device__ float g_seglist[NCLS*SEGCAP*8]; // kept entries {s, j, x1, y1}{x2, y2, 0, 0}
__device__ int   g_segcnt[NCLS];
__device__ float g_dsc[NTOT];             // dense kept scores (final phase)
__device__ int   g_done;

__device__ __forceinline__ unsigned int mono_key(float s) {
    unsigned int b = __float_as_uint(s);
    return (b & 0x80000000u) ? ~b : (b | 0x80000000u);
}
__device__ __forceinline__ float inv_mono(unsigned int u) {
    unsigned int b = (u & 0x80000000u) ? (u & 0x7FFFFFFFu) : ~u;
    return __uint_as_float(b);
}

struct SMem {
    unsigned long long skey[2048];
    float sx1[CAP], sy1[CAP], sx2[CAP], sy2[CAP], sar[CAP], ssc[CAP];
    unsigned long long smask[MASK_CAP*8];  // reused as sup[] bytes in fallback
    unsigned long long skeep[24];
    int   cnt;
    int   kcnt;
    int   offs[NCLS+1];
};

__device__ __forceinline__ void decode_one(const float* __restrict__ rois,
                                           const float* __restrict__ delta,
                                           int idx, int cls, float s,
                                           float lx, float ly,
                                           SMem& sm, int r) {
    float x1 = rois[idx*5+1], y1 = rois[idx*5+2];
    float x2 = rois[idx*5+3], y2 = rois[idx*5+4];
    float w  = x2 - x1 + 1.0f;
    float h  = y2 - y1 + 1.0f;
    float cx = x1 + 0.5f*w;
    float cy = y1 + 0.5f*h;

    const float4 d4 = *reinterpret_cast<const float4*>(delta + (size_t)idx*(4*81) + 4*cls);
    float dx = d4.x / 10.0f, dy = d4.y / 10.0f;
    float dw = d4.z / 5.0f,  dh = d4.w / 5.0f;

    float pcx = cx + w*dx;
    float pcy = cy + h*dy;
    float pw  = w * expf(dw);
    float ph  = h * expf(dh);

    float bx1 = fminf(fmaxf(pcx - 0.5f*pw,        0.0f), lx);
    float by1 = fminf(fmaxf(pcy - 0.5f*ph,        0.0f), ly);
    float bx2 = fminf(fmaxf(pcx + 0.5f*pw - 1.0f, 0.0f), lx);
    float by2 = fminf(fmaxf(pcy + 0.5f*ph - 1.0f, 0.0f), ly);

    sm.sx1[r] = bx1; sm.sy1[r] = by1; sm.sx2[r] = bx2; sm.sy2[r] = by2;
    sm.sar[r] = (bx2 - bx1 + 1.0f) * (by2 - by1 + 1.0f);
    sm.ssc[r] = s;
}

__global__ __launch_bounds__(THREADS) void k_all(const float* __restrict__ rois,
                                                 const float* __restrict__ delta,
                                                 const float* __restrict__ prob,
                                                 const float* __restrict__ iminfo,
                                                 float* __restrict__ out) {
    extern __shared__ char smem_raw[];
    SMem& sm = *reinterpret_cast<SMem*>(smem_raw);
    const int c   = blockIdx.x;
    const int cls = c + 1;
    const int tid = threadIdx.x;

    if (tid == 0) { sm.cnt = 0; sm.kcnt = 0; }
    __syncthreads();

    // ---- fill this block's 1/NCLS slice of the output ----
    // layout (float32): dets[NTOT*6]=0 | cls_idx[NTOT]=class | keep[NTOT]=0
    {
        float4* o4 = reinterpret_cast<float4*>(out);
        const int q0 = c*QPB, q1 = q0 + QPB;
        for (int q = q0 + tid; q < q1; q += THREADS) {
            float4 v = make_float4(0.f,0.f,0.f,0.f);
            if (q >= (NTOT*6)/4 && q < (NTOT*7)/4) {
                int r0 = q*4 - NTOT*6;
                v.x = (float)((r0+0)/NROI + 1);
                v.y = (float)((r0+1)/NROI + 1);
                v.z = (float)((r0+2)/NROI + 1);
                v.w = (float)((r0+3)/NROI + 1);
            }
            o4[q] = v;
        }
    }

    // ---- compact valid entries as (score,idx) keys ----
    for (int j = tid; j < NROI; j += THREADS) {
        float s = prob[(size_t)j*81 + cls];
        if (s > SCORE_THRESH) {
            int p = atomicAdd(&sm.cnt, 1);
            sm.skey[p] = ((unsigned long long)mono_key(s) << 32)
                       | (unsigned long long)(0xFFFFFFFFu - (unsigned)j);
        }
    }
    __syncthreads();
    const int nv = sm.cnt;

    if (nv > 0) {
        const float H = iminfo[0], W = iminfo[1];
        const float lx = W - 1.0f, ly = H - 1.0f;

        if (nv <= RANK_CAP) {
            // ---- rank sort: descending rank = #{keys > mine}; keys unique ----
            for (int j = tid; j < nv; j += THREADS) {
                unsigned long long k = sm.skey[j];
                int r = 0;
                for (int i = 0; i < nv; i++) r += (sm.skey[i] > k);
                int idx = (int)(0xFFFFFFFFu - (unsigned int)(k & 0xFFFFFFFFull));
                float s = inv_mono((unsigned int)(k >> 32));
                decode_one(rois, delta, idx, cls, s, lx, ly, sm, r);
            }
            __syncthreads();
        } else {
            // ---- fallback: bitonic sort over m = next pow2 >= nv ----
            int m = 1; while (m < nv) m <<= 1;
            for (int j = nv + tid; j < m; j += THREADS) sm.skey[j] = 0ull; // pads last
            __syncthreads();
            for (int size = 2; size <= m; size <<= 1) {
                for (int stride = size >> 1; stride > 0; stride >>= 1) {
                    for (int t = tid; t < (m >> 1); t += THREADS) {
                        int pos = 2*t - (t & (stride - 1));
                        bool desc = (pos & size) == 0;
                        unsigned long long a = sm.skey[pos], b = sm.skey[pos + stride];
                        if ((a < b) == desc) { sm.skey[pos] = b; sm.skey[pos + stride] = a; }
                    }
                    __syncthreads();
                }
            }
            for (int j = tid; j < nv; j += THREADS) {
                unsigned long long k = sm.skey[j];
                int idx = (int)(0xFFFFFFFFu - (unsigned int)(k & 0xFFFFFFFFull));
                float s = inv_mono((unsigned int)(k >> 32));
                decode_one(rois, delta, idx, cls, s, lx, ly, sm, j);
            }
            __syncthreads();
        }

        // ---- NMS ----
        if (nv <= MASK_CAP) {
            const int MW = (nv + 63) >> 6;
            for (int i = tid; i < nv; i += THREADS) {
                float x1 = sm.sx1[i], y1 = sm.sy1[i], x2 = sm.sx2[i], y2 = sm.sy2[i];
                float ai = sm.sar[i];
                unsigned long long row[8];
                #pragma unroll
                for (int w = 0; w < 8; w++) row[w] = 0ull;
                for (int j = i + 1; j < nv; j++) {
                    float iw = fminf(x2, sm.sx2[j]) - fmaxf(x1, sm.sx1[j]) + 1.0f;
                    float ih = fminf(y2, sm.sy2[j]) - fmaxf(y1, sm.sy1[j]) + 1.0f;
                    iw = fmaxf(iw, 0.0f);
                    ih = fmaxf(ih, 0.0f);
                    float inter = iw * ih;
                    float iou = inter / (ai + sm.sar[j] - inter);
                    if (iou > NMS_THRESH) row[j >> 6] |= (1ull << (j & 63));
                }
                #pragma unroll
                for (int w = 0; w < 8; w++) sm.smask[i*8 + w] = row[w];
            }
            __syncthreads();
            if (tid == 0) {
                unsigned long long keepw[8], supw[8];
                #pragma unroll
                for (int w = 0; w < 8; w++) { keepw[w] = 0ull; supw[w] = 0ull; }
                for (int i = 0; i < nv; i++) {
                    if (!((supw[i >> 6] >> (i & 63)) & 1ull)) {
                        keepw[i >> 6] |= (1ull << (i & 63));
                        for (int w = (i >> 6); w < MW; w++) supw[w] |= sm.smask[i*8 + w];
                    }
                }
                for (int w = 0; w < MW; w++) sm.skeep[w] = keepw[w];
            }
            __syncthreads();
        } else {
            unsigned char* sup = reinterpret_cast<unsigned char*>(sm.smask);
            for (int j = tid; j < nv; j += THREADS) sup[j] = 0;
            if (tid < 24) sm.skeep[tid] = 0ull;
            __syncthreads();
            int i = 0;
            while (i < nv) {
                if (tid == 0) sm.skeep[i >> 6] |= (1ull << (i & 63));
                float x1 = sm.sx1[i], y1 = sm.sy1[i], x2 = sm.sx2[i], y2 = sm.sy2[i];
                float ai = sm.sar[i];
                for (int j = i + 1 + tid; j < nv; j += THREADS) {
                    if (sup[j]) continue;
                    float iw = fminf(x2, sm.sx2[j]) - fmaxf(x1, sm.sx1[j]) + 1.0f;
                    float ih = fminf(y2, sm.sy2[j]) - fmaxf(y1, sm.sy1[j]) + 1.0f;
                    iw = fmaxf(iw, 0.0f);
                    ih = fmaxf(ih, 0.0f);
                    float inter = iw * ih;
                    float iou = inter / (ai + sm.sar[j] - inter);
                    if (iou > NMS_THRESH) sup[j] = 1;
                }
                __syncthreads();
                ++i;
                while (i < nv && sup[i]) ++i;
            }
        }

        // ---- append kept entries to this class's PRIVATE segment ----
        for (int j = tid; j < nv; j += THREADS) {
            if ((sm.skeep[j >> 6] >> (j & 63)) & 1ull) {
                int p = atomicAdd(&sm.kcnt, 1);          // shared atomic: cheap
                g_segsc[c*SEGCAP + p] = sm.ssc[j];
                float4* L = reinterpret_cast<float4*>(g_seglist + (size_t)(c*SEGCAP + p)*8);
                L[0] = make_float4(sm.ssc[j], (float)j, sm.sx1[j], sm.sy1[j]);
                L[1] = make_float4(sm.sx2[j], sm.sy2[j], 0.f, 0.f);
            }
        }
    }
    __syncthreads();
    if (tid == 0) g_segcnt[c] = sm.kcnt;   // written every run, even 0

    // ================= last-block final phase =================
    __threadfence();
    __shared__ int s_last;
    if (tid == 0) s_last = (atomicAdd(&g_done, 1) == NCLS - 1);
    __syncthreads();
    if (!s_last) return;
    __threadfence();

    const int lane = tid & 31, w = tid >> 5;
    const int NW = THREADS/32;

    // offsets over per-class counts
    if (tid == 0) {
        int acc = 0;
        for (int k = 0; k < NCLS; k++) { sm.offs[k] = acc; acc += g_segcnt[k]; }
        sm.offs[NCLS] = acc;
    }
    __syncthreads();
    const int count = sm.offs[NCLS];

    // dense copy of kept scores (warp per class, strided)
    for (int cc = w; cc < NCLS; cc += NW) {
        int off = sm.offs[cc], n = sm.offs[cc+1] - off;
        for (int k = lane; k < n; k += 32)
            g_dsc[off + k] = g_segsc[cc*SEGCAP + k];
    }
    __syncthreads();
    __threadfence();   // g_dsc visible block-wide (same SM; fence for safety)

    int   filt = 0;
    float kth  = -CUDART_INF_F;

    if (count > MAX_DET) {
        // radix select over the monotone key: 4 levels of 8-bit digits
        __shared__ int hist[256];
        __shared__ int wtot[8];
        __shared__ unsigned int s_prefix;
        __shared__ int s_need;
        if (tid == 0) { s_prefix = 0u; s_need = MAX_DET; }
        __syncthreads();

        #pragma unroll
        for (int level = 0; level < 4; ++level) {
            const int shift = 24 - 8*level;
            const unsigned int dmask = (level == 0) ? 0u : (0xFFFFFFFFu << (shift + 8));
            if (tid < 256) hist[tid] = 0;
            __syncthreads();
            const unsigned int pfx = s_prefix;
            const int need = s_need;
            for (int j = tid; j < count; j += THREADS) {
                unsigned int u = mono_key(g_dsc[j]);   // L2-hot
                if ((u & dmask) == pfx)
                    atomicAdd(&hist[(u >> shift) & 0xFFu], 1);
            }
            __syncthreads();
            if (tid < 256) {
                int h = hist[tid];
                // warp suffix scan (8 warps x 32 bins)
                int v = h;
                #pragma unroll
                for (int off = 1; off < 32; off <<= 1) {
                    int u = __shfl_down_sync(0xFFFFFFFFu, v, off);
                    if (lane + off < 32) v += u;
                }
                if (lane == 0) wtot[w] = v;
                __syncthreads();
                int add = 0;
                #pragma unroll
                for (int k = 0; k < 8; k++) if (k > w) add += wtot[k];
                int sfx = v + add;            // sum of hist[tid..255]
                int hi  = sfx - h;            // sum of hist[tid+1..255]
                if (sfx >= need && hi < need) {   // unique chosen bin
                    s_prefix = pfx | ((unsigned int)tid << shift);
                    s_need   = need - hi;
                }
            } else {
                __syncthreads();
            }
            __syncthreads();
        }
        filt = 1;
        kth  = inv_mono(s_prefix);        // exact value of the MAX_DET-th largest
    }

    // ---- scatter kept rows from segments into the output ----
    for (int cc = w; cc < NCLS; cc += NW) {
        int n = sm.offs[cc+1] - sm.offs[cc];
        for (int k = lane; k < n; k += 32) {
            const float4 L0 = reinterpret_cast<const float4*>(g_seglist + (size_t)(cc*SEGCAP + k)*8)[0];
            float s = L0.x;
            if (filt && !(s >= kth)) continue;
            const float4 L1 = reinterpret_cast<const float4*>(g_seglist + (size_t)(cc*SEGCAP + k)*8)[1];
            int jj = (int)L0.y;
            int r = cc*NROI + jj;
            float* d = out + (size_t)r*6;
            d[0] = 0.0f;
            d[1] = L0.z;  // x1
            d[2] = L0.w;  // y1
            d[3] = L1.x;  // x2
            d[4] = L1.y;  // y2
            d[5] = s;
            out[NTOT*7 + r] = 1.0f;   // keep flag
        }
    }

    // ---- restore invariants for the next invocation ----
    __syncthreads();
    if (tid == 0) g_done = 0;
}

extern "C" void kernel_launch(void* const* d_in, const int* in_sizes, int n_in,
                              void* d_out, int out_size) {
    const float* rois   = (const float*)d_in[0];
    const float* delta  = (const float*)d_in[1];
    const float* prob   = (const float*)d_in[2];
    const float* iminfo = (const float*)d_in[3];
    float* out = (float*)d_out;

    static_assert(sizeof(SMem) < 100*1024, "smem budget");
    cudaFuncSetAttribute(k_all, cudaFuncAttributeMaxDynamicSharedMemorySize,
                         (int)sizeof(SMem));

    k_all<<<NCLS, THREADS, sizeof(SMem)>>>(rois, delta, prob, iminfo, out);
}